// round 7
// baseline (speedup 1.0000x reference)
#include <cuda_runtime.h>
#include <cstddef>

namespace {

constexpr int B = 8, T = 2048, H = 256, L = 16;
constexpr int S = 32;                  // t-strip per block
constexpr int WARPS = 4;               // warp g owns l in [4g, 4g+3]
constexpr int THREADS = WARPS * 32;    // 128
constexpr int STRIPS_PER_B = T / S;    // 64
constexpr int NBLOCKS = B * STRIPS_PER_B;  // 512

struct R8 { float v[8]; };
struct TrueT  { static constexpr bool value = true;  };
struct FalseT { static constexpr bool value = false; };

// Load 8 consecutive floats of row `row` (this lane's H-slice).
// CHK=true: zeros when row OOB (implements the reference's zero padding).
template <bool CHK>
__device__ __forceinline__ R8 load_row8(const float* __restrict__ base, int row, int hbase) {
  R8 r;
  if (!CHK || (unsigned)row < (unsigned)T) {
    const float4* p = reinterpret_cast<const float4*>(base + (size_t)row * H + hbase);
    float4 a = p[0];
    float4 b = p[1];
    r.v[0] = a.x; r.v[1] = a.y; r.v[2] = a.z; r.v[3] = a.w;
    r.v[4] = b.x; r.v[5] = b.y; r.v[6] = b.z; r.v[7] = b.w;
  } else {
#pragma unroll
    for (int j = 0; j < 8; j++) r.v[j] = 0.f;
  }
  return r;
}

// Interleaved merge: lanes with (lane&s)==0 end up carrying the a-class
// partial sum, lanes with (lane&s)!=0 the b-class. One shfl per merge.
__device__ __forceinline__ float shfl_merge(float a, float b, int s, int lane) {
  const bool hi = (lane & s) != 0;
  float send = hi ? a : b;            // what the partner needs
  float recv = __shfl_xor_sync(0xffffffffu, send, s);
  return (hi ? b : a) + recv;
}

__global__ __launch_bounds__(THREADS)
void ffm_kernel(const float* __restrict__ logits,
                const float* __restrict__ end_w,
                const float* __restrict__ whole_w,
                const float* __restrict__ relay_w,
                const float* __restrict__ relay_b,
                const float* __restrict__ length_bias,
                float* __restrict__ out,
                float* __restrict__ relay_out) {
  const int strip = blockIdx.x;
  const int b     = strip / STRIPS_PER_B;
  const int s0    = (strip % STRIPS_PER_B) * S;
  const int g     = threadIdx.x >> 5;   // warp id: l in [4g, 4g+3]
  const int lane  = threadIdx.x & 31;
  const int hbase = lane * 8;

  // Weights in registers for the whole strip.
  float w0[8], w1[8], w2[8], w3[8], ew[8], rw[8];
#pragma unroll
  for (int q = 0; q < 2; q++) {
    float4 x0 = *reinterpret_cast<const float4*>(whole_w + (4 * g + 0) * H + hbase + 4 * q);
    float4 x1 = *reinterpret_cast<const float4*>(whole_w + (4 * g + 1) * H + hbase + 4 * q);
    float4 x2 = *reinterpret_cast<const float4*>(whole_w + (4 * g + 2) * H + hbase + 4 * q);
    float4 x3 = *reinterpret_cast<const float4*>(whole_w + (4 * g + 3) * H + hbase + 4 * q);
    float4 xe = *reinterpret_cast<const float4*>(end_w + hbase + 4 * q);
    float4 xr = *reinterpret_cast<const float4*>(relay_w + hbase + 4 * q);
    w0[4*q+0]=x0.x; w0[4*q+1]=x0.y; w0[4*q+2]=x0.z; w0[4*q+3]=x0.w;
    w1[4*q+0]=x1.x; w1[4*q+1]=x1.y; w1[4*q+2]=x1.z; w1[4*q+3]=x1.w;
    w2[4*q+0]=x2.x; w2[4*q+1]=x2.y; w2[4*q+2]=x2.z; w2[4*q+3]=x2.w;
    w3[4*q+0]=x3.x; w3[4*q+1]=x3.y; w3[4*q+2]=x3.z; w3[4*q+3]=x3.w;
    ew[4*q+0]=xe.x; ew[4*q+1]=xe.y; ew[4*q+2]=xe.z; ew[4*q+3]=xe.w;
    rw[4*q+0]=xr.x; rw[4*q+1]=xr.y; rw[4*q+2]=xr.z; rw[4*q+3]=xr.w;
  }
  // Final tree classes: bit16+2*bit8 select l, bit4 selects t offset.
  const int  l_idx  = ((lane >> 4) & 1) + ((lane >> 3) & 1) * 2;
  const int  t_off  = (lane >> 2) & 1;
  const bool writer = (lane & 3) == 0;
  const float bias  = length_bias[4 * g + l_idx];
  const float rb    = relay_b[0];

  const float* lb = logits + (size_t)b * T * H;

  auto body = [&](auto chk_tag) {
    constexpr bool CHK = decltype(chk_tag)::value;

    // 4-row circular window. At (even) step u, p = u & 3: slot p holds row
    // r-4g; slot (p-k)&3 holds row r-4g-k for k=1..3.
    R8 Wn[4];
#pragma unroll
    for (int k = 1; k <= 3; k++)
      Wn[(4 - k) & 3] = load_row8<CHK>(lb, s0 - 4 * g - k, hbase);

    for (int u0 = 0; u0 < S; u0 += 4) {
#pragma unroll
      for (int pp = 0; pp < 2; pp++) {
        const int u = u0 + 2 * pp;
        const int p = u & 3;            // 0 or 2 (compile-time per unrolled copy)
        const int r = s0 + u;

        // All loads for the pair issued up-front (max MLP).
        R8 row0 = load_row8<CHK>(lb, r - 4 * g, hbase);      // window row, t=r
        R8 row1 = load_row8<CHK>(lb, r + 1 - 4 * g, hbase);  // window row, t=r+1
        R8 cur0, cur1, nxt0, nxt1;
        if (g == 0) {
          cur0 = row0;
          cur1 = row1;
          nxt0 = load_row8<CHK>(lb, r + L, hbase);
          nxt1 = load_row8<CHK>(lb, r + L + 1, hbase);
        } else {
          cur0 = load_row8<false>(lb, r, hbase);
          cur1 = load_row8<false>(lb, r + 1, hbase);
        }

        Wn[p] = row0;

        // t = r. Slot (p+1)&3 still holds row r-4g-3 — consumed here before
        // being overwritten below.
        float e0 = 0.f, a0 = 0.f, a1 = 0.f, a2 = 0.f, a3 = 0.f;
#pragma unroll
        for (int j = 0; j < 8; j++) {
          const float c = cur0.v[j];
          e0 = fmaf(c, ew[j], e0);
          a0 = fmaf(fmaxf(c, Wn[p].v[j]),           w0[j], a0);
          a1 = fmaf(fmaxf(c, Wn[(p + 3) & 3].v[j]), w1[j], a1);
          a2 = fmaf(fmaxf(c, Wn[(p + 2) & 3].v[j]), w2[j], a2);
          a3 = fmaf(fmaxf(c, Wn[(p + 1) & 3].v[j]), w3[j], a3);
        }

        Wn[(p + 1) & 3] = row1;  // advance window for t = r+1

        // t = r+1 (window index base p+1).
        float e1 = 0.f, b0 = 0.f, b1 = 0.f, b2 = 0.f, b3 = 0.f;
#pragma unroll
        for (int j = 0; j < 8; j++) {
          const float c = cur1.v[j];
          e1 = fmaf(c, ew[j], e1);
          b0 = fmaf(fmaxf(c, Wn[(p + 1) & 3].v[j]), w0[j], b0);
          b1 = fmaf(fmaxf(c, Wn[p].v[j]),           w1[j], b1);
          b2 = fmaf(fmaxf(c, Wn[(p + 3) & 3].v[j]), w2[j], b2);
          b3 = fmaf(fmaxf(c, Wn[(p + 2) & 3].v[j]), w3[j], b3);
        }

        // Fold end-score partials (lane-sum distributes over the reduction).
        a0 += e0; a1 += e0; a2 += e0; a3 += e0;
        b0 += e1; b1 += e1; b2 += e1; b3 += e1;

        // Fused 8-value interleaved tree: 9 shfls for 8 outputs.
        float x0 = shfl_merge(a0, a1, 16, lane);
        float x1 = shfl_merge(a2, a3, 16, lane);
        float y0 = shfl_merge(b0, b1, 16, lane);
        float y1 = shfl_merge(b2, b3, 16, lane);
        float x  = shfl_merge(x0, x1, 8, lane);
        float y  = shfl_merge(y0, y1, 8, lane);
        float z  = shfl_merge(x, y, 4, lane);    // bit4: 0 → t=r, 1 → t=r+1
        z += __shfl_xor_sync(0xffffffffu, z, 2);
        z += __shfl_xor_sync(0xffffffffu, z, 1);

        if (writer)
          out[(size_t)(b * T + r + t_off) * L + 4 * g + l_idx] = z + bias;

        if (g == 0) {  // relay for t = r and t = r+1, one fused chain
          float rel0 = 0.f, rel1 = 0.f;
#pragma unroll
          for (int j = 0; j < 8; j++) {
            rel0 = fmaf(fmaxf(cur0.v[j], nxt0.v[j]), rw[j], rel0);
            rel1 = fmaf(fmaxf(cur1.v[j], nxt1.v[j]), rw[j], rel1);
          }
          float m = shfl_merge(rel0, rel1, 16, lane);  // bit16 selects t
          m += __shfl_xor_sync(0xffffffffu, m, 8);
          m += __shfl_xor_sync(0xffffffffu, m, 4);
          m += __shfl_xor_sync(0xffffffffu, m, 2);
          m += __shfl_xor_sync(0xffffffffu, m, 1);
          if ((lane & 15) == 0)
            relay_out[(size_t)b * T + r + (lane >> 4)] = m + rb;
        }
      }
    }
  };

  // Interior strips touch rows [s0-15, s0+S-1+L+1] ⊂ [0, T): skip checks.
  const bool interior = (s0 > 0) && (s0 + S + L + 1 <= T);
  if (interior) body(FalseT{});
  else          body(TrueT{});
}

}  // namespace

extern "C" void kernel_launch(void* const* d_in, const int* in_sizes, int n_in,
                              void* d_out, int out_size) {
  const float* logits  = (const float*)d_in[0];
  const float* end_w   = (const float*)d_in[1];
  const float* whole_w = (const float*)d_in[2];
  const float* relay_w = (const float*)d_in[3];
  const float* relay_b = (const float*)d_in[4];
  const float* lbias   = (const float*)d_in[5];

  float* out   = (float*)d_out;                // [B, T, L]
  float* relay = out + (size_t)B * T * L;      // [B, T] appended

  ffm_kernel<<<NBLOCKS, THREADS>>>(logits, end_w, whole_w, relay_w, relay_b,
                                   lbias, out, relay);
}

// round 8
// speedup vs baseline: 1.1632x; 1.1632x over previous
#include <cuda_runtime.h>
#include <cstddef>

namespace {

constexpr int B = 8, T = 2048, H = 256, L = 16;
constexpr int S = 16;                  // t-strip per block (halved: grid-limited occ)
constexpr int WARPS = 4;               // warp g owns l in [4g, 4g+3]
constexpr int THREADS = WARPS * 32;    // 128
constexpr int STRIPS_PER_B = T / S;    // 128
constexpr int NBLOCKS = B * STRIPS_PER_B;  // 1024

struct R8 { float v[8]; };
struct TrueT  { static constexpr bool value = true;  };
struct FalseT { static constexpr bool value = false; };

// Load 8 consecutive floats of row `row` (this lane's H-slice).
// CHK=true: zeros when row OOB (implements the reference's zero padding).
template <bool CHK>
__device__ __forceinline__ R8 load_row8(const float* __restrict__ base, int row, int hbase) {
  R8 r;
  if (!CHK || (unsigned)row < (unsigned)T) {
    const float4* p = reinterpret_cast<const float4*>(base + (size_t)row * H + hbase);
    float4 a = p[0];
    float4 b = p[1];
    r.v[0] = a.x; r.v[1] = a.y; r.v[2] = a.z; r.v[3] = a.w;
    r.v[4] = b.x; r.v[5] = b.y; r.v[6] = b.z; r.v[7] = b.w;
  } else {
#pragma unroll
    for (int j = 0; j < 8; j++) r.v[j] = 0.f;
  }
  return r;
}

// Interleaved merge: lanes with (lane&s)==0 end up carrying the a-class
// partial sum, lanes with (lane&s)!=0 the b-class. One shfl per merge.
__device__ __forceinline__ float shfl_merge(float a, float b, int s, int lane) {
  const bool hi = (lane & s) != 0;
  float send = hi ? a : b;            // what the partner needs
  float recv = __shfl_xor_sync(0xffffffffu, send, s);
  return (hi ? b : a) + recv;
}

__global__ __launch_bounds__(THREADS)
void ffm_kernel(const float* __restrict__ logits,
                const float* __restrict__ end_w,
                const float* __restrict__ whole_w,
                const float* __restrict__ relay_w,
                const float* __restrict__ relay_b,
                const float* __restrict__ length_bias,
                float* __restrict__ out,
                float* __restrict__ relay_out) {
  const int strip = blockIdx.x;
  const int b     = strip / STRIPS_PER_B;
  const int s0    = (strip % STRIPS_PER_B) * S;
  const int g     = threadIdx.x >> 5;   // warp id: l in [4g, 4g+3]
  const int lane  = threadIdx.x & 31;
  const int hbase = lane * 8;

  // Weights in registers for the whole strip.
  float w0[8], w1[8], w2[8], w3[8], ew[8], rw[8];
#pragma unroll
  for (int q = 0; q < 2; q++) {
    float4 x0 = *reinterpret_cast<const float4*>(whole_w + (4 * g + 0) * H + hbase + 4 * q);
    float4 x1 = *reinterpret_cast<const float4*>(whole_w + (4 * g + 1) * H + hbase + 4 * q);
    float4 x2 = *reinterpret_cast<const float4*>(whole_w + (4 * g + 2) * H + hbase + 4 * q);
    float4 x3 = *reinterpret_cast<const float4*>(whole_w + (4 * g + 3) * H + hbase + 4 * q);
    float4 xe = *reinterpret_cast<const float4*>(end_w + hbase + 4 * q);
    float4 xr = *reinterpret_cast<const float4*>(relay_w + hbase + 4 * q);
    w0[4*q+0]=x0.x; w0[4*q+1]=x0.y; w0[4*q+2]=x0.z; w0[4*q+3]=x0.w;
    w1[4*q+0]=x1.x; w1[4*q+1]=x1.y; w1[4*q+2]=x1.z; w1[4*q+3]=x1.w;
    w2[4*q+0]=x2.x; w2[4*q+1]=x2.y; w2[4*q+2]=x2.z; w2[4*q+3]=x2.w;
    w3[4*q+0]=x3.x; w3[4*q+1]=x3.y; w3[4*q+2]=x3.z; w3[4*q+3]=x3.w;
    ew[4*q+0]=xe.x; ew[4*q+1]=xe.y; ew[4*q+2]=xe.z; ew[4*q+3]=xe.w;
    rw[4*q+0]=xr.x; rw[4*q+1]=xr.y; rw[4*q+2]=xr.z; rw[4*q+3]=xr.w;
  }
  // Writer-lane mapping: lanes 0,16,8,24 hold finished sums for
  // l = 4g + idx with idx = ((lane>>4)&1) + ((lane>>3)&1)*2.
  const int  idx    = ((lane >> 4) & 1) + ((lane >> 3) & 1) * 2;
  const bool writer = (lane & 7) == 0;
  const float bias  = length_bias[4 * g + idx];
  const float rb    = relay_b[0];

  const float* lb = logits + (size_t)b * T * H;

  auto body = [&](auto chk_tag) {
    constexpr bool CHK = decltype(chk_tag)::value;

    // 4-row register window. Row (s0 + u - 4g) loaded at step u into slot u&3;
    // at step u (p = u & 3), row r-4g-k lives in slot (p - k) & 3.
    R8 Wn[4];
#pragma unroll
    for (int k = 1; k <= 3; k++)
      Wn[(4 - k) & 3] = load_row8<CHK>(lb, s0 - 4 * g - k, hbase);

    for (int u0 = 0; u0 < S; u0 += 4) {
#pragma unroll
      for (int p = 0; p < 4; p++) {
        const int r = s0 + u0 + p;

        Wn[p] = load_row8<CHK>(lb, r - 4 * g, hbase);  // advance window
        R8 cur, nxt;
        if (g == 0) {
          cur = Wn[p];                                 // warp 0: window row IS row r
          nxt = load_row8<CHK>(lb, r + L, hbase);      // relay partner row
        } else {
          cur = load_row8<false>(lb, r, hbase);        // row r always in-bounds
        }

        float e = 0.f, a0 = 0.f, a1 = 0.f, a2 = 0.f, a3 = 0.f;
#pragma unroll
        for (int j = 0; j < 8; j++) {
          const float c = cur.v[j];
          e  = fmaf(c, ew[j], e);
          a0 = fmaf(fmaxf(c, Wn[p].v[j]),           w0[j], a0);  // l = 4g
          a1 = fmaf(fmaxf(c, Wn[(p + 3) & 3].v[j]), w1[j], a1);  // l = 4g+1
          a2 = fmaf(fmaxf(c, Wn[(p + 2) & 3].v[j]), w2[j], a2);  // l = 4g+2
          a3 = fmaf(fmaxf(c, Wn[(p + 1) & 3].v[j]), w3[j], a3);  // l = 4g+3
        }
        // Fold end-score partial into each acc (lane-sum distributes).
        a0 += e; a1 += e; a2 += e; a3 += e;

        // Interleaved 4-value warp reduction: 5 shfl total.
        float x = shfl_merge(a0, a1, 16, lane);   // bit16: 0→a0, 1→a1
        float y = shfl_merge(a2, a3, 16, lane);   // bit16: 0→a2, 1→a3
        float z = shfl_merge(x,  y,  8,  lane);   // bit8:  0→x,  1→y
        z += __shfl_xor_sync(0xffffffffu, z, 4);
        z += __shfl_xor_sync(0xffffffffu, z, 2);
        z += __shfl_xor_sync(0xffffffffu, z, 1);

        if (writer)
          out[(size_t)(b * T + r) * L + 4 * g + idx] = z + bias;

        if (g == 0) {  // relay for t = r
          float rel = 0.f;
#pragma unroll
          for (int j = 0; j < 8; j++)
            rel = fmaf(fmaxf(cur.v[j], nxt.v[j]), rw[j], rel);
#pragma unroll
          for (int s = 16; s > 0; s >>= 1)
            rel += __shfl_xor_sync(0xffffffffu, rel, s);
          if (lane == 0) relay_out[(size_t)b * T + r] = rel + rb;
        }
      }
    }
  };

  // Interior strips touch rows [s0-15, s0+S-1+L] ⊂ [0, T): skip bounds checks.
  const bool interior = (s0 >= 16) && (s0 + S + L <= T);
  if (interior) body(FalseT{});
  else          body(TrueT{});
}

}  // namespace

extern "C" void kernel_launch(void* const* d_in, const int* in_sizes, int n_in,
                              void* d_out, int out_size) {
  const float* logits  = (const float*)d_in[0];
  const float* end_w   = (const float*)d_in[1];
  const float* whole_w = (const float*)d_in[2];
  const float* relay_w = (const float*)d_in[3];
  const float* relay_b = (const float*)d_in[4];
  const float* lbias   = (const float*)d_in[5];

  float* out   = (float*)d_out;                // [B, T, L]
  float* relay = out + (size_t)B * T * L;      // [B, T] appended

  ffm_kernel<<<NBLOCKS, THREADS>>>(logits, end_w, whole_w, relay_w, relay_b,
                                   lbias, out, relay);
}

// round 9
// speedup vs baseline: 1.2771x; 1.0979x over previous
#include <cuda_runtime.h>
#include <cstddef>

namespace {

constexpr int B = 8, T = 2048, H = 256, L = 16;
constexpr int S = 16;                  // t-strip per main block
constexpr int WARPS = 4;               // warp g owns l in [4g, 4g+3]
constexpr int THREADS = WARPS * 32;    // 128
constexpr int STRIPS_PER_B = T / S;    // 128
constexpr int MAIN_BLOCKS  = B * STRIPS_PER_B;    // 1024
constexpr int RELAY_BLOCKS = 128;                  // 512 warps x 32 t = 16384
constexpr int GRID = MAIN_BLOCKS + RELAY_BLOCKS;   // 1152
constexpr int RELAY_T_PER_WARP = (B * T) / (RELAY_BLOCKS * WARPS);  // 32

struct R8 { float v[8]; };
struct TrueT  { static constexpr bool value = true;  };
struct FalseT { static constexpr bool value = false; };

// Load 8 consecutive floats of row `row` (this lane's H-slice).
// CHK=true: zeros when row OOB (implements the reference's zero padding).
template <bool CHK>
__device__ __forceinline__ R8 load_row8(const float* __restrict__ base, int row, int hbase) {
  R8 r;
  if (!CHK || (unsigned)row < (unsigned)T) {
    const float4* p = reinterpret_cast<const float4*>(base + (size_t)row * H + hbase);
    float4 a = p[0];
    float4 b = p[1];
    r.v[0] = a.x; r.v[1] = a.y; r.v[2] = a.z; r.v[3] = a.w;
    r.v[4] = b.x; r.v[5] = b.y; r.v[6] = b.z; r.v[7] = b.w;
  } else {
#pragma unroll
    for (int j = 0; j < 8; j++) r.v[j] = 0.f;
  }
  return r;
}

// Interleaved merge: lanes with (lane&s)==0 carry the a-class partial sum,
// lanes with (lane&s)!=0 the b-class. One shfl per merge.
__device__ __forceinline__ float shfl_merge(float a, float b, int s, int lane) {
  const bool hi = (lane & s) != 0;
  float send = hi ? a : b;
  float recv = __shfl_xor_sync(0xffffffffu, send, s);
  return (hi ? b : a) + recv;
}

__global__ __launch_bounds__(THREADS, 5)
void ffm_kernel(const float* __restrict__ logits,
                const float* __restrict__ end_w,
                const float* __restrict__ whole_w,
                const float* __restrict__ relay_w,
                const float* __restrict__ relay_b,
                const float* __restrict__ length_bias,
                float* __restrict__ out,
                float* __restrict__ relay_out) {
  const int g    = threadIdx.x >> 5;
  const int lane = threadIdx.x & 31;
  const int hbase = lane * 8;

  if (blockIdx.x >= MAIN_BLOCKS) {
    // ---------------- relay blocks ----------------
    // relay[b,t] = sum_h max(x[b,t,h], x_pad[b,t+L,h]) * relay_w[h] + relay_b
    const int wglob = (blockIdx.x - MAIN_BLOCKS) * WARPS + g;   // [0, 512)
    const int base_t = wglob * RELAY_T_PER_WARP;                // within one b
    const int b  = base_t / T;
    const int t0 = base_t % T;
    const float* lb = logits + (size_t)b * T * H;

    float rw[8];
#pragma unroll
    for (int q = 0; q < 2; q++) {
      float4 xr = *reinterpret_cast<const float4*>(relay_w + hbase + 4 * q);
      rw[4*q+0]=xr.x; rw[4*q+1]=xr.y; rw[4*q+2]=xr.z; rw[4*q+3]=xr.w;
    }
    const float rb = relay_b[0];

    for (int k = 0; k < RELAY_T_PER_WARP; k += 2) {
      const int t = t0 + k;
      R8 cur0 = load_row8<false>(lb, t, hbase);
      R8 cur1 = load_row8<false>(lb, t + 1, hbase);
      R8 nxt0 = load_row8<true>(lb, t + L, hbase);
      R8 nxt1 = load_row8<true>(lb, t + L + 1, hbase);

      float rel0 = 0.f, rel1 = 0.f;
#pragma unroll
      for (int j = 0; j < 8; j++) {
        rel0 = fmaf(fmaxf(cur0.v[j], nxt0.v[j]), rw[j], rel0);
        rel1 = fmaf(fmaxf(cur1.v[j], nxt1.v[j]), rw[j], rel1);
      }
      float m = shfl_merge(rel0, rel1, 16, lane);  // bit16: 0→t, 1→t+1
      m += __shfl_xor_sync(0xffffffffu, m, 8);
      m += __shfl_xor_sync(0xffffffffu, m, 4);
      m += __shfl_xor_sync(0xffffffffu, m, 2);
      m += __shfl_xor_sync(0xffffffffu, m, 1);
      if ((lane & 15) == 0)
        relay_out[(size_t)b * T + t + (lane >> 4)] = m + rb;
    }
    return;
  }

  // ---------------- main blocks ----------------
  const int strip = blockIdx.x;
  const int b     = strip / STRIPS_PER_B;
  const int s0    = (strip % STRIPS_PER_B) * S;

  // Weights in registers for the whole strip.
  float w0[8], w1[8], w2[8], w3[8], ew[8];
#pragma unroll
  for (int q = 0; q < 2; q++) {
    float4 x0 = *reinterpret_cast<const float4*>(whole_w + (4 * g + 0) * H + hbase + 4 * q);
    float4 x1 = *reinterpret_cast<const float4*>(whole_w + (4 * g + 1) * H + hbase + 4 * q);
    float4 x2 = *reinterpret_cast<const float4*>(whole_w + (4 * g + 2) * H + hbase + 4 * q);
    float4 x3 = *reinterpret_cast<const float4*>(whole_w + (4 * g + 3) * H + hbase + 4 * q);
    float4 xe = *reinterpret_cast<const float4*>(end_w + hbase + 4 * q);
    w0[4*q+0]=x0.x; w0[4*q+1]=x0.y; w0[4*q+2]=x0.z; w0[4*q+3]=x0.w;
    w1[4*q+0]=x1.x; w1[4*q+1]=x1.y; w1[4*q+2]=x1.z; w1[4*q+3]=x1.w;
    w2[4*q+0]=x2.x; w2[4*q+1]=x2.y; w2[4*q+2]=x2.z; w2[4*q+3]=x2.w;
    w3[4*q+0]=x3.x; w3[4*q+1]=x3.y; w3[4*q+2]=x3.z; w3[4*q+3]=x3.w;
    ew[4*q+0]=xe.x; ew[4*q+1]=xe.y; ew[4*q+2]=xe.z; ew[4*q+3]=xe.w;
  }
  // Writer lanes 0,16,8,24 hold finished sums for l = 4g + idx,
  // idx = bit16 + 2*bit8.
  const int  idx    = ((lane >> 4) & 1) + ((lane >> 3) & 1) * 2;
  const bool writer = (lane & 7) == 0;
  const float bias  = length_bias[4 * g + idx];

  const float* lb = logits + (size_t)b * T * H;

  auto body = [&](auto chk_tag) {
    constexpr bool CHK = decltype(chk_tag)::value;

    // 4-row register window. Row (s0 + u - 4g) loaded at step u into slot u&3;
    // at step u (p = u & 3), row r-4g-k lives in slot (p - k) & 3.
    R8 Wn[4];
#pragma unroll
    for (int k = 1; k <= 3; k++)
      Wn[(4 - k) & 3] = load_row8<CHK>(lb, s0 - 4 * g - k, hbase);

#pragma unroll
    for (int u = 0; u < S; u++) {
      const int p = u & 3;
      const int r = s0 + u;

      Wn[p] = load_row8<CHK>(lb, r - 4 * g, hbase);  // advance window
      R8 cur;
      if (g == 0) cur = Wn[p];                       // warp 0: window row IS row r
      else        cur = load_row8<false>(lb, r, hbase);

      float e = 0.f, a0 = 0.f, a1 = 0.f, a2 = 0.f, a3 = 0.f;
#pragma unroll
      for (int j = 0; j < 8; j++) {
        const float c = cur.v[j];
        e  = fmaf(c, ew[j], e);
        a0 = fmaf(fmaxf(c, Wn[p].v[j]),           w0[j], a0);  // l = 4g
        a1 = fmaf(fmaxf(c, Wn[(p + 3) & 3].v[j]), w1[j], a1);  // l = 4g+1
        a2 = fmaf(fmaxf(c, Wn[(p + 2) & 3].v[j]), w2[j], a2);  // l = 4g+2
        a3 = fmaf(fmaxf(c, Wn[(p + 1) & 3].v[j]), w3[j], a3);  // l = 4g+3
      }
      // Fold end-score partial into each acc (lane-sum distributes).
      a0 += e; a1 += e; a2 += e; a3 += e;

      // Interleaved 4-value warp reduction: 5 shfl total.
      float x = shfl_merge(a0, a1, 16, lane);
      float y = shfl_merge(a2, a3, 16, lane);
      float z = shfl_merge(x,  y,  8,  lane);
      z += __shfl_xor_sync(0xffffffffu, z, 4);
      z += __shfl_xor_sync(0xffffffffu, z, 2);
      z += __shfl_xor_sync(0xffffffffu, z, 1);

      if (writer)
        out[(size_t)(b * T + r) * L + 4 * g + idx] = z + bias;
    }
  };

  // Max row touched is s0+S-1 < T; only rows below 0 need checks → s0 == 0.
  if (s0 >= 16) body(FalseT{});
  else          body(TrueT{});
}

}  // namespace

extern "C" void kernel_launch(void* const* d_in, const int* in_sizes, int n_in,
                              void* d_out, int out_size) {
  const float* logits  = (const float*)d_in[0];
  const float* end_w   = (const float*)d_in[1];
  const float* whole_w = (const float*)d_in[2];
  const float* relay_w = (const float*)d_in[3];
  const float* relay_b = (const float*)d_in[4];
  const float* lbias   = (const float*)d_in[5];

  float* out   = (float*)d_out;                // [B, T, L]
  float* relay = out + (size_t)B * T * L;      // [B, T] appended

  ffm_kernel<<<GRID, THREADS>>>(logits, end_w, whole_w, relay_w, relay_b,
                                lbias, out, relay);
}

// round 10
// speedup vs baseline: 1.2927x; 1.0122x over previous
#include <cuda_runtime.h>
#include <cstddef>

namespace {

constexpr int B = 8, T = 2048, H = 256, L = 16;
constexpr int S = 16;                  // t-strip per main block
constexpr int WARPS = 4;               // warp g owns l in [4g, 4g+3]
constexpr int THREADS = WARPS * 32;    // 128
constexpr int STRIPS_PER_B = T / S;    // 128
constexpr int MAIN_BLOCKS  = B * STRIPS_PER_B;    // 1024
constexpr int RELAY_BLOCKS = 128;                  // 512 warps x 32 t = 16384
constexpr int GRID = MAIN_BLOCKS + RELAY_BLOCKS;   // 1152
constexpr int RELAY_T_PER_WARP = (B * T) / (RELAY_BLOCKS * WARPS);  // 32

struct R8 { float v[8]; };
struct TrueT  { static constexpr bool value = true;  };
struct FalseT { static constexpr bool value = false; };

// Load 8 consecutive floats of row `row` (this lane's H-slice).
// CHK=true: zeros when row OOB (implements the reference's zero padding).
template <bool CHK>
__device__ __forceinline__ R8 load_row8(const float* __restrict__ base, int row, int hbase) {
  R8 r;
  if (!CHK || (unsigned)row < (unsigned)T) {
    const float4* p = reinterpret_cast<const float4*>(base + (size_t)row * H + hbase);
    float4 a = p[0];
    float4 b = p[1];
    r.v[0] = a.x; r.v[1] = a.y; r.v[2] = a.z; r.v[3] = a.w;
    r.v[4] = b.x; r.v[5] = b.y; r.v[6] = b.z; r.v[7] = b.w;
  } else {
#pragma unroll
    for (int j = 0; j < 8; j++) r.v[j] = 0.f;
  }
  return r;
}

// Interleaved merge: lanes with (lane&s)==0 carry the a-class partial sum,
// lanes with (lane&s)!=0 the b-class. One shfl per merge.
__device__ __forceinline__ float shfl_merge(float a, float b, int s, int lane) {
  const bool hi = (lane & s) != 0;
  float send = hi ? a : b;
  float recv = __shfl_xor_sync(0xffffffffu, send, s);
  return (hi ? b : a) + recv;
}

__global__ __launch_bounds__(THREADS, 4)
void ffm_kernel(const float* __restrict__ logits,
                const float* __restrict__ end_w,
                const float* __restrict__ whole_w,
                const float* __restrict__ relay_w,
                const float* __restrict__ relay_b,
                const float* __restrict__ length_bias,
                float* __restrict__ out,
                float* __restrict__ relay_out) {
  const int g    = threadIdx.x >> 5;
  const int lane = threadIdx.x & 31;
  const int hbase = lane * 8;

  if (blockIdx.x >= MAIN_BLOCKS) {
    // ---------------- relay blocks ----------------
    // relay[b,t] = sum_h max(x[b,t,h], x_pad[b,t+L,h]) * relay_w[h] + relay_b
    const int wglob = (blockIdx.x - MAIN_BLOCKS) * WARPS + g;   // [0, 512)
    const int base_t = wglob * RELAY_T_PER_WARP;
    const int b  = base_t / T;
    const int t0 = base_t % T;
    const float* lb = logits + (size_t)b * T * H;

    float rw[8];
#pragma unroll
    for (int q = 0; q < 2; q++) {
      float4 xr = *reinterpret_cast<const float4*>(relay_w + hbase + 4 * q);
      rw[4*q+0]=xr.x; rw[4*q+1]=xr.y; rw[4*q+2]=xr.z; rw[4*q+3]=xr.w;
    }
    const float rb = relay_b[0];

    for (int k = 0; k < RELAY_T_PER_WARP; k += 2) {
      const int t = t0 + k;
      R8 cur0 = load_row8<false>(lb, t, hbase);
      R8 cur1 = load_row8<false>(lb, t + 1, hbase);
      R8 nxt0 = load_row8<true>(lb, t + L, hbase);
      R8 nxt1 = load_row8<true>(lb, t + L + 1, hbase);

      float rel0 = 0.f, rel1 = 0.f;
#pragma unroll
      for (int j = 0; j < 8; j++) {
        rel0 = fmaf(fmaxf(cur0.v[j], nxt0.v[j]), rw[j], rel0);
        rel1 = fmaf(fmaxf(cur1.v[j], nxt1.v[j]), rw[j], rel1);
      }
      float m = shfl_merge(rel0, rel1, 16, lane);  // bit16: 0→t, 1→t+1
      m += __shfl_xor_sync(0xffffffffu, m, 8);
      m += __shfl_xor_sync(0xffffffffu, m, 4);
      m += __shfl_xor_sync(0xffffffffu, m, 2);
      m += __shfl_xor_sync(0xffffffffu, m, 1);
      if ((lane & 15) == 0)
        relay_out[(size_t)b * T + t + (lane >> 4)] = m + rb;
    }
    return;
  }

  // ---------------- main blocks ----------------
  const int strip = blockIdx.x;
  const int b     = strip / STRIPS_PER_B;
  const int s0    = (strip % STRIPS_PER_B) * S;

  // Weights in registers for the whole strip.
  float w0[8], w1[8], w2[8], w3[8], ew[8];
#pragma unroll
  for (int q = 0; q < 2; q++) {
    float4 x0 = *reinterpret_cast<const float4*>(whole_w + (4 * g + 0) * H + hbase + 4 * q);
    float4 x1 = *reinterpret_cast<const float4*>(whole_w + (4 * g + 1) * H + hbase + 4 * q);
    float4 x2 = *reinterpret_cast<const float4*>(whole_w + (4 * g + 2) * H + hbase + 4 * q);
    float4 x3 = *reinterpret_cast<const float4*>(whole_w + (4 * g + 3) * H + hbase + 4 * q);
    float4 xe = *reinterpret_cast<const float4*>(end_w + hbase + 4 * q);
    w0[4*q+0]=x0.x; w0[4*q+1]=x0.y; w0[4*q+2]=x0.z; w0[4*q+3]=x0.w;
    w1[4*q+0]=x1.x; w1[4*q+1]=x1.y; w1[4*q+2]=x1.z; w1[4*q+3]=x1.w;
    w2[4*q+0]=x2.x; w2[4*q+1]=x2.y; w2[4*q+2]=x2.z; w2[4*q+3]=x2.w;
    w3[4*q+0]=x3.x; w3[4*q+1]=x3.y; w3[4*q+2]=x3.z; w3[4*q+3]=x3.w;
    ew[4*q+0]=xe.x; ew[4*q+1]=xe.y; ew[4*q+2]=xe.z; ew[4*q+3]=xe.w;
  }
  // Final tree classes: l_idx = bit16 + 2*bit8, t chosen by bit4.
  const int  l_idx  = ((lane >> 4) & 1) + ((lane >> 3) & 1) * 2;
  const int  t_off  = (lane >> 2) & 1;
  const bool writer = (lane & 3) == 0;
  const float bias  = length_bias[4 * g + l_idx];

  const float* lb = logits + (size_t)b * T * H;

  auto body = [&](auto chk_tag) {
    constexpr bool CHK = decltype(chk_tag)::value;

    // 4-row circular window. At even step u (p = u & 3): slot (p-k)&3 holds
    // row r-4g-k for k=1..3; Wn[p] receives row r-4g.
    R8 Wn[4];
#pragma unroll
    for (int k = 1; k <= 3; k++)
      Wn[(4 - k) & 3] = load_row8<CHK>(lb, s0 - 4 * g - k, hbase);

#pragma unroll
    for (int u = 0; u < S; u += 2) {
      const int p = u & 3;            // 0 or 2, compile-time under full unroll
      const int r = s0 + u;

      // All loads for the pair issued up-front (max MLP).
      R8 row0 = load_row8<CHK>(lb, r - 4 * g, hbase);      // window row, t=r
      R8 row1 = load_row8<CHK>(lb, r + 1 - 4 * g, hbase);  // window row, t=r+1
      R8 cur0, cur1;
      if (g == 0) {
        cur0 = row0;
        cur1 = row1;
      } else {
        cur0 = load_row8<false>(lb, r, hbase);
        cur1 = load_row8<false>(lb, r + 1, hbase);
      }

      Wn[p] = row0;

      // t = r. Slot (p+1)&3 still holds row r-4g-3 — consumed before being
      // overwritten below.
      float e0 = 0.f, a0 = 0.f, a1 = 0.f, a2 = 0.f, a3 = 0.f;
#pragma unroll
      for (int j = 0; j < 8; j++) {
        const float c = cur0.v[j];
        e0 = fmaf(c, ew[j], e0);
        a0 = fmaf(fmaxf(c, Wn[p].v[j]),           w0[j], a0);
        a1 = fmaf(fmaxf(c, Wn[(p + 3) & 3].v[j]), w1[j], a1);
        a2 = fmaf(fmaxf(c, Wn[(p + 2) & 3].v[j]), w2[j], a2);
        a3 = fmaf(fmaxf(c, Wn[(p + 1) & 3].v[j]), w3[j], a3);
      }

      Wn[(p + 1) & 3] = row1;  // advance window for t = r+1

      // t = r+1 (window index base p+1).
      float e1 = 0.f, b0 = 0.f, b1 = 0.f, b2 = 0.f, b3 = 0.f;
#pragma unroll
      for (int j = 0; j < 8; j++) {
        const float c = cur1.v[j];
        e1 = fmaf(c, ew[j], e1);
        b0 = fmaf(fmaxf(c, Wn[(p + 1) & 3].v[j]), w0[j], b0);
        b1 = fmaf(fmaxf(c, Wn[p].v[j]),           w1[j], b1);
        b2 = fmaf(fmaxf(c, Wn[(p + 3) & 3].v[j]), w2[j], b2);
        b3 = fmaf(fmaxf(c, Wn[(p + 2) & 3].v[j]), w3[j], b3);
      }

      // Fold end-score partials (lane-sum distributes over the reduction).
      a0 += e0; a1 += e0; a2 += e0; a3 += e0;
      b0 += e1; b1 += e1; b2 += e1; b3 += e1;

      // Fused 8-value interleaved tree: 9 shfls for 8 outputs.
      float x0 = shfl_merge(a0, a1, 16, lane);
      float x1 = shfl_merge(a2, a3, 16, lane);
      float y0 = shfl_merge(b0, b1, 16, lane);
      float y1 = shfl_merge(b2, b3, 16, lane);
      float x  = shfl_merge(x0, x1, 8, lane);
      float y  = shfl_merge(y0, y1, 8, lane);
      float z  = shfl_merge(x, y, 4, lane);    // bit4: 0 → t=r, 1 → t=r+1
      z += __shfl_xor_sync(0xffffffffu, z, 2);
      z += __shfl_xor_sync(0xffffffffu, z, 1);

      if (writer)
        out[(size_t)(b * T + r + t_off) * L + 4 * g + l_idx] = z + bias;
    }
  };

  // Min row touched is s0-15 (warp 3 prefill); max row s0+S-1 < T.
  if (s0 >= 16) body(FalseT{});
  else          body(TrueT{});
}

}  // namespace

extern "C" void kernel_launch(void* const* d_in, const int* in_sizes, int n_in,
                              void* d_out, int out_size) {
  const float* logits  = (const float*)d_in[0];
  const float* end_w   = (const float*)d_in[1];
  const float* whole_w = (const float*)d_in[2];
  const float* relay_w = (const float*)d_in[3];
  const float* relay_b = (const float*)d_in[4];
  const float* lbias   = (const float*)d_in[5];

  float* out   = (float*)d_out;                // [B, T, L]
  float* relay = out + (size_t)B * T * L;      // [B, T] appended

  ffm_kernel<<<GRID, THREADS>>>(logits, end_w, whole_w, relay_w, relay_b,
                                lbias, out, relay);
}